// round 3
// baseline (speedup 1.0000x reference)
#include <cuda_runtime.h>
#include <cuda_bf16.h>

#define C_IN 64
#define C_OUT 128
#define BEV_H 512
#define BEV_W 512

// One warp per point. Lane l accumulates output channels [4l, 4l+3].
__global__ void bev_conv_kernel(const int* __restrict__ coords,
                                const float* __restrict__ feats,
                                const float* __restrict__ kernel,
                                const int* __restrict__ stride_p,
                                float* __restrict__ out,
                                int n_points)
{
    int warp_id = (blockIdx.x * blockDim.x + threadIdx.x) >> 5;
    int lane = threadIdx.x & 31;
    if (warp_id >= n_points) return;

    const int stride = stride_p[0];

    // coords row: [x, h, z, b]
    int4 c4 = ((const int4*)coords)[warp_id];
    int x = c4.x / stride;
    int kidx = c4.y / stride;
    int z = c4.z / stride;
    int b = c4.w;

    // Each lane holds two feature values; broadcast via shuffle in K loop.
    const float* fp = feats + (size_t)warp_id * C_IN;
    float f0 = fp[lane];
    float f1 = fp[lane + 32];

    // Weight matrix for this kernel bin, viewed as rows of 32 float4 (128 ch).
    const float4* kp = (const float4*)(kernel + (size_t)kidx * C_IN * C_OUT);

    float4 acc = make_float4(0.f, 0.f, 0.f, 0.f);
#pragma unroll
    for (int k = 0; k < C_IN; k++) {
        float fk = __shfl_sync(0xFFFFFFFFu, (k < 32) ? f0 : f1, k & 31);
        float4 w = kp[k * (C_OUT / 4) + lane];
        acc.x = fmaf(fk, w.x, acc.x);
        acc.y = fmaf(fk, w.y, acc.y);
        acc.z = fmaf(fk, w.z, acc.z);
        acc.w = fmaf(fk, w.w, acc.w);
    }

    // out[b, c, x, z], c = 4*lane + j
    size_t plane = (size_t)BEV_H * BEV_W;
    size_t base = (size_t)b * C_OUT * plane + (size_t)x * BEV_W + (size_t)z;
    size_t coff = base + (size_t)(lane * 4) * plane;
    atomicAdd(&out[coff + 0 * plane], acc.x);
    atomicAdd(&out[coff + 1 * plane], acc.y);
    atomicAdd(&out[coff + 2 * plane], acc.z);
    atomicAdd(&out[coff + 3 * plane], acc.w);
}

extern "C" void kernel_launch(void* const* d_in, const int* in_sizes, int n_in,
                              void* d_out, int out_size)
{
    const int*   coords = (const int*)d_in[0];
    const float* feats  = (const float*)d_in[1];
    const float* kern   = (const float*)d_in[2];
    const int*   stride = (const int*)d_in[3];

    int n_points = in_sizes[1] / C_IN;

    // Zero the 256MB output (poisoned by harness). Async memset is capturable.
    cudaMemsetAsync(d_out, 0, (size_t)out_size * sizeof(float));

    // One warp per point: 8 warps (256 threads) per block.
    int warps_per_block = 8;
    int blocks = (n_points + warps_per_block - 1) / warps_per_block;
    bev_conv_kernel<<<blocks, warps_per_block * 32>>>(
        coords, feats, kern, stride, (float*)d_out, n_points);
}

// round 4
// speedup vs baseline: 1.6487x; 1.6487x over previous
#include <cuda_runtime.h>
#include <cuda_bf16.h>

#define C_IN   64
#define C_OUT  128
#define BEV_H  512
#define BEV_W  512
#define BATCH  2

#define N_CELLS      (BATCH * BEV_H * BEV_W)        // 524288
#define BITMAP_WORDS (N_CELLS / 32)                 // 16384

// Channel-contiguous scratch: [cell][C_OUT]. 256 MB, zero-init at module load;
// per-launch we only re-zero touched cells (tracked by bitmap).
__device__ float        g_scratch[(size_t)N_CELLS * C_OUT];
__device__ unsigned int g_bitmap[BITMAP_WORDS];

// ---------------------------------------------------------------- bitmap clear
__global__ void clear_bitmap_kernel()
{
    int i = blockIdx.x * blockDim.x + threadIdx.x;
    if (i < BITMAP_WORDS) g_bitmap[i] = 0u;
}

// ------------------------------------------- zero touched scratch cells + mark
// One warp per point: 32 lanes x float4 = 512B = full cell.
__global__ void zero_cells_kernel(const int* __restrict__ coords,
                                  const int* __restrict__ stride_p,
                                  int n_points)
{
    int wid  = (blockIdx.x * blockDim.x + threadIdx.x) >> 5;
    int lane = threadIdx.x & 31;
    if (wid >= n_points) return;

    int s  = stride_p[0];
    int4 c4 = ((const int4*)coords)[wid];
    int cell = c4.w * (BEV_H * BEV_W) + (c4.x / s) * BEV_W + (c4.z / s);

    float4 z = make_float4(0.f, 0.f, 0.f, 0.f);
    ((float4*)g_scratch)[(size_t)cell * (C_OUT / 4) + lane] = z;

    if (lane == 0)
        atomicOr(&g_bitmap[cell >> 5], 1u << (cell & 31));
}

// --------------------------------------------------- matvec + coalesced scatter
// One warp per point. Lane l accumulates channels [4l,4l+3] and atomically adds
// them to a CONTIGUOUS 512B scratch cell (sector-dense, L2-resident).
__global__ void scatter_kernel(const int* __restrict__ coords,
                               const float* __restrict__ feats,
                               const float* __restrict__ kernel,
                               const int* __restrict__ stride_p,
                               int n_points)
{
    int wid  = (blockIdx.x * blockDim.x + threadIdx.x) >> 5;
    int lane = threadIdx.x & 31;
    if (wid >= n_points) return;

    int s  = stride_p[0];
    int4 c4 = ((const int4*)coords)[wid];
    int cell = c4.w * (BEV_H * BEV_W) + (c4.x / s) * BEV_W + (c4.z / s);
    int kidx = c4.y / s;

    const float* fp = feats + (size_t)wid * C_IN;
    float f0 = fp[lane];
    float f1 = fp[lane + 32];

    const float4* kp = (const float4*)(kernel + (size_t)kidx * C_IN * C_OUT);

    float4 acc = make_float4(0.f, 0.f, 0.f, 0.f);
#pragma unroll
    for (int k = 0; k < C_IN; k++) {
        float fk = __shfl_sync(0xFFFFFFFFu, (k < 32) ? f0 : f1, k & 31);
        float4 w = kp[k * (C_OUT / 4) + lane];
        acc.x = fmaf(fk, w.x, acc.x);
        acc.y = fmaf(fk, w.y, acc.y);
        acc.z = fmaf(fk, w.z, acc.z);
        acc.w = fmaf(fk, w.w, acc.w);
    }

    float* dst = g_scratch + (size_t)cell * C_OUT + lane * 4;
    atomicAdd(dst + 0, acc.x);
    atomicAdd(dst + 1, acc.y);
    atomicAdd(dst + 2, acc.z);
    atomicAdd(dst + 3, acc.w);
}

// ------------------------------------------------------- expand / transpose out
// One block per (b, x) row. Streams the full output with coalesced float4
// stores; empty cells (bitmap bit clear) write zeros without touching scratch.
__global__ void expand_kernel(float* __restrict__ out)
{
    int row = blockIdx.x;              // b * BEV_H + x
    int b   = row >> 9;
    int x   = row & (BEV_H - 1);

    __shared__ unsigned int bits[BEV_W / 32];   // 16 words
    int tid = threadIdx.x;
    if (tid < BEV_W / 32) bits[tid] = g_bitmap[row * (BEV_W / 32) + tid];
    __syncthreads();

    int q     = tid & 127;             // float4 index along z (0..127)
    int cpair = tid >> 7;              // 0 or 1
    int z0    = q * 4;
    unsigned occ = (bits[z0 >> 5] >> (z0 & 31)) & 0xFu;

    const float* srow = g_scratch + (size_t)row * BEV_W * C_OUT;

#pragma unroll 4
    for (int cb = 0; cb < C_OUT; cb += 2) {
        int c = cb + cpair;
        float4 v;
        v.x = (occ & 1u) ? srow[(size_t)(z0 + 0) * C_OUT + c] : 0.f;
        v.y = (occ & 2u) ? srow[(size_t)(z0 + 1) * C_OUT + c] : 0.f;
        v.z = (occ & 4u) ? srow[(size_t)(z0 + 2) * C_OUT + c] : 0.f;
        v.w = (occ & 8u) ? srow[(size_t)(z0 + 3) * C_OUT + c] : 0.f;
        size_t o = (((size_t)(b * C_OUT + c) * BEV_H + x) * BEV_W) >> 2;
        ((float4*)out)[o + q] = v;
    }
}

extern "C" void kernel_launch(void* const* d_in, const int* in_sizes, int n_in,
                              void* d_out, int out_size)
{
    const int*   coords = (const int*)d_in[0];
    const float* feats  = (const float*)d_in[1];
    const float* kern   = (const float*)d_in[2];
    const int*   stride = (const int*)d_in[3];

    int n_points = in_sizes[1] / C_IN;

    // 1. clear occupancy bitmap (64 KB)
    clear_bitmap_kernel<<<(BITMAP_WORDS + 255) / 256, 256>>>();

    // 2. zero only the touched scratch cells, mark bitmap
    int wpb = 8;
    int blocks = (n_points + wpb - 1) / wpb;
    zero_cells_kernel<<<blocks, wpb * 32>>>(coords, stride, n_points);

    // 3. matvec + coalesced atomic scatter into scratch
    scatter_kernel<<<blocks, wpb * 32>>>(coords, feats, kern, stride, n_points);

    // 4. stream final output (writes every element -> no memset needed)
    expand_kernel<<<BATCH * BEV_H, 256>>>((float*)d_out);
}